// round 2
// baseline (speedup 1.0000x reference)
#include <cuda_runtime.h>
#include <cstdint>

// Problem constants (fixed by the dataset)
#define NNODES 50000
#define NEDGES 800000
#define INC    512
#define HIDC   256
#define OUTC   64

// ---------------- scratch (device globals; no allocation allowed) ----------
__device__ __align__(16) float g_h1[NNODES * HIDC];      // x @ W1
__device__ __align__(16) float g_a1[NNODES * HIDC];      // relu(aggregate(h1) + b1)
__device__ __align__(16) float g_h2[NNODES * OUTC];      // a1 @ W2
__device__ float g_dinv[NNODES];
__device__ int   g_deg[NNODES];
__device__ int   g_rowptr[NNODES + 1];
__device__ int   g_pos[NNODES];
__device__ int   g_csr_src[NEDGES];
__device__ float g_csr_nrm[NEDGES];

// ---------------- degree / CSR construction -------------------------------
__global__ void k_init_deg() {
    int v = blockIdx.x * blockDim.x + threadIdx.x;
    if (v < NNODES) g_deg[v] = 1;  // self loop
}

__global__ void k_count(const int* __restrict__ dst, int E) {
    int e = blockIdx.x * blockDim.x + threadIdx.x;
    if (e < E) atomicAdd(&g_deg[dst[e]], 1);
}

__global__ void k_dinv() {
    int v = blockIdx.x * blockDim.x + threadIdx.x;
    if (v < NNODES) g_dinv[v] = rsqrtf((float)g_deg[v]);
}

// one-block exclusive scan over edge counts (deg-1) -> rowptr, pos
__global__ void k_scan() {
    __shared__ int sums[1024];
    const int CHUNK = (NNODES + 1023) / 1024;  // 49
    int tid = threadIdx.x;
    int start = tid * CHUNK;
    int end = min(start + CHUNK, NNODES);
    int s = 0;
    for (int v = start; v < end; v++) s += g_deg[v] - 1;
    sums[tid] = s;
    __syncthreads();
    if (tid == 0) {
        int acc = 0;
        for (int i = 0; i < 1024; i++) { int t = sums[i]; sums[i] = acc; acc += t; }
    }
    __syncthreads();
    int acc = sums[tid];
    for (int v = start; v < end; v++) {
        g_rowptr[v] = acc;
        g_pos[v]    = acc;
        acc += g_deg[v] - 1;
    }
    if (end == NNODES && start < NNODES) g_rowptr[NNODES] = acc;
}

__global__ void k_scatter(const int* __restrict__ src,
                          const int* __restrict__ dst, int E) {
    int e = blockIdx.x * blockDim.x + threadIdx.x;
    if (e >= E) return;
    int s = src[e];
    int d = dst[e];
    int p = atomicAdd(&g_pos[d], 1);
    g_csr_src[p] = s;
    g_csr_nrm[p] = g_dinv[s] * g_dinv[d];
}

// ---------------- fp32 register-tiled GEMM (C = A[M,K] @ B[K,N]) ----------
// BM=64, BN=64, BK=16, 256 threads, 4x4 per thread
__device__ __forceinline__ void gemm_body(const float* __restrict__ A,
                                          const float* __restrict__ B,
                                          float* __restrict__ C,
                                          int M, int K, int Ncol) {
    __shared__ float As[16][64];
    __shared__ float Bs[16][64];

    const int tid = threadIdx.x;
    const int tx = tid & 15;       // 0..15 -> 4 cols each
    const int ty = tid >> 4;       // 0..15 -> 4 rows each
    const int rowBase = blockIdx.y * 64;
    const int colBase = blockIdx.x * 64;

    float acc[4][4];
#pragma unroll
    for (int i = 0; i < 4; i++)
#pragma unroll
        for (int j = 0; j < 4; j++) acc[i][j] = 0.f;

    for (int k0 = 0; k0 < K; k0 += 16) {
        // load A tile (transposed into smem): 64x16 = 1024 elems
#pragma unroll
        for (int i = tid; i < 64 * 16; i += 256) {
            int m = i >> 4;
            int k = i & 15;
            int gm = rowBase + m;
            As[k][m] = (gm < M) ? A[(size_t)gm * K + k0 + k] : 0.f;
        }
        // load B tile: 16x64
#pragma unroll
        for (int i = tid; i < 16 * 64; i += 256) {
            int k = i >> 6;
            int n = i & 63;
            Bs[k][n] = B[(size_t)(k0 + k) * Ncol + colBase + n];
        }
        __syncthreads();

#pragma unroll
        for (int kk = 0; kk < 16; kk++) {
            float4 a4 = *reinterpret_cast<const float4*>(&As[kk][ty * 4]);
            float4 b4 = *reinterpret_cast<const float4*>(&Bs[kk][tx * 4]);
            float a[4] = {a4.x, a4.y, a4.z, a4.w};
            float b[4] = {b4.x, b4.y, b4.z, b4.w};
#pragma unroll
            for (int i = 0; i < 4; i++)
#pragma unroll
                for (int j = 0; j < 4; j++) acc[i][j] += a[i] * b[j];
        }
        __syncthreads();
    }

#pragma unroll
    for (int i = 0; i < 4; i++) {
        int row = rowBase + ty * 4 + i;
        if (row < M) {
            float4 o = make_float4(acc[i][0], acc[i][1], acc[i][2], acc[i][3]);
            *reinterpret_cast<float4*>(&C[(size_t)row * Ncol + colBase + tx * 4]) = o;
        }
    }
}

__global__ __launch_bounds__(256) void k_gemm1(const float* __restrict__ A,
                                               const float* __restrict__ B) {
    gemm_body(A, B, g_h1, NNODES, INC, HIDC);
}

__global__ __launch_bounds__(256) void k_gemm2(const float* __restrict__ B) {
    gemm_body(g_a1, B, g_h2, NNODES, HIDC, OUTC);
}

// ---------------- layer-1 aggregation: warp per node, 256 channels --------
__global__ __launch_bounds__(256) void k_agg1(const float* __restrict__ b1) {
    int warp = (blockIdx.x * blockDim.x + threadIdx.x) >> 5;
    int lane = threadIdx.x & 31;
    if (warp >= NNODES) return;
    const int v = warp;

    float4 acc0 = make_float4(0.f, 0.f, 0.f, 0.f);
    float4 acc1 = acc0;

    const int beg = g_rowptr[v];
    const int end = g_rowptr[v + 1];
    for (int e = beg; e < end; e++) {
        int s = g_csr_src[e];
        float w = g_csr_nrm[e];
        const float4* hs = reinterpret_cast<const float4*>(g_h1 + (size_t)s * HIDC);
        float4 x0 = hs[lane];
        float4 x1 = hs[32 + lane];
        acc0.x += w * x0.x; acc0.y += w * x0.y; acc0.z += w * x0.z; acc0.w += w * x0.w;
        acc1.x += w * x1.x; acc1.y += w * x1.y; acc1.z += w * x1.z; acc1.w += w * x1.w;
    }
    // self loop
    {
        float dv = g_dinv[v];
        float w = dv * dv;
        const float4* hv = reinterpret_cast<const float4*>(g_h1 + (size_t)v * HIDC);
        float4 x0 = hv[lane];
        float4 x1 = hv[32 + lane];
        acc0.x += w * x0.x; acc0.y += w * x0.y; acc0.z += w * x0.z; acc0.w += w * x0.w;
        acc1.x += w * x1.x; acc1.y += w * x1.y; acc1.z += w * x1.z; acc1.w += w * x1.w;
    }
    const float4* bb = reinterpret_cast<const float4*>(b1);
    float4 c0 = bb[lane];
    float4 c1 = bb[32 + lane];
    float4 o0 = make_float4(fmaxf(acc0.x + c0.x, 0.f), fmaxf(acc0.y + c0.y, 0.f),
                            fmaxf(acc0.z + c0.z, 0.f), fmaxf(acc0.w + c0.w, 0.f));
    float4 o1 = make_float4(fmaxf(acc1.x + c1.x, 0.f), fmaxf(acc1.y + c1.y, 0.f),
                            fmaxf(acc1.z + c1.z, 0.f), fmaxf(acc1.w + c1.w, 0.f));
    float4* outp = reinterpret_cast<float4*>(g_a1 + (size_t)v * HIDC);
    outp[lane] = o0;
    outp[32 + lane] = o1;
}

// ------- layer-2 aggregation + bias + log_softmax, warp per node ----------
__global__ __launch_bounds__(256) void k_agg2(const float* __restrict__ b2,
                                              float* __restrict__ out) {
    int warp = (blockIdx.x * blockDim.x + threadIdx.x) >> 5;
    int lane = threadIdx.x & 31;
    if (warp >= NNODES) return;
    const int v = warp;

    float2 acc = make_float2(0.f, 0.f);
    const int beg = g_rowptr[v];
    const int end = g_rowptr[v + 1];
    for (int e = beg; e < end; e++) {
        int s = g_csr_src[e];
        float w = g_csr_nrm[e];
        const float2* hs = reinterpret_cast<const float2*>(g_h2 + (size_t)s * OUTC);
        float2 x = hs[lane];
        acc.x += w * x.x;
        acc.y += w * x.y;
    }
    {
        float dv = g_dinv[v];
        float w = dv * dv;
        const float2* hv = reinterpret_cast<const float2*>(g_h2 + (size_t)v * OUTC);
        float2 x = hv[lane];
        acc.x += w * x.x;
        acc.y += w * x.y;
    }
    const float2* bb = reinterpret_cast<const float2*>(b2);
    float2 c = bb[lane];
    float v0 = acc.x + c.x;
    float v1 = acc.y + c.y;

    // warp-wide log_softmax over 64 channels (2 per lane)
    float m = fmaxf(v0, v1);
#pragma unroll
    for (int o = 16; o > 0; o >>= 1) m = fmaxf(m, __shfl_xor_sync(0xFFFFFFFFu, m, o));
    float s = expf(v0 - m) + expf(v1 - m);
#pragma unroll
    for (int o = 16; o > 0; o >>= 1) s += __shfl_xor_sync(0xFFFFFFFFu, s, o);
    float ls = logf(s);

    float2 ov = make_float2(v0 - m - ls, v1 - m - ls);
    reinterpret_cast<float2*>(out)[(size_t)v * 32 + lane] = ov;
}

// ---------------- launch --------------------------------------------------
extern "C" void kernel_launch(void* const* d_in, const int* in_sizes, int n_in,
                              void* d_out, int out_size) {
    const float* x  = (const float*)d_in[0];
    const int*   ei = (const int*)d_in[1];    // JAX default config: int64 -> int32
    const float* W1 = (const float*)d_in[2];
    const float* b1 = (const float*)d_in[3];
    const float* W2 = (const float*)d_in[4];
    const float* b2 = (const float*)d_in[5];
    float* out = (float*)d_out;

    const int E = in_sizes[1] / 2;  // 800000
    const int* src = ei;
    const int* dst = ei + E;

    const int TB = 256;
    const int nodeBlocks = (NNODES + TB - 1) / TB;
    const int edgeBlocks = (E + TB - 1) / TB;
    const int warpBlocks = (NNODES * 32 + TB - 1) / TB;  // warp per node

    // CSR build (every call; deterministic modulo atomic edge order)
    k_init_deg<<<nodeBlocks, TB>>>();
    k_count<<<edgeBlocks, TB>>>(dst, E);
    k_dinv<<<nodeBlocks, TB>>>();
    k_scan<<<1, 1024>>>();
    k_scatter<<<edgeBlocks, TB>>>(src, dst, E);

    // layer 1
    dim3 g1(HIDC / 64, (NNODES + 63) / 64);
    k_gemm1<<<g1, 256>>>(x, W1);
    k_agg1<<<warpBlocks, TB>>>(b1);

    // layer 2
    dim3 g2(OUTC / 64, (NNODES + 63) / 64);
    k_gemm2<<<g2, 256>>>(W2);
    k_agg2<<<warpBlocks, TB>>>(b2, out);
}

// round 5
// speedup vs baseline: 2.7187x; 2.7187x over previous
#include <cuda_runtime.h>
#include <cuda_bf16.h>
#include <cstdint>

// Problem constants (fixed by the dataset)
#define NNODES 50000
#define NEDGES 800000
#define INC    512
#define HIDC   256
#define OUTC   64

// ---------------- scratch (device globals; no allocation allowed) ----------
__device__ __align__(16) float g_h1[NNODES * HIDC];      // x @ W1
__device__ __align__(16) float g_a1[NNODES * HIDC];      // relu(agg(h1) + b1)
__device__ __align__(16) float g_h2[NNODES * OUTC];      // a1 @ W2
__device__ __align__(16) __nv_bfloat16 g_w1h[HIDC * INC];  // W1^T hi  [256 n][512 k]
__device__ __align__(16) __nv_bfloat16 g_w1l[HIDC * INC];  // W1^T lo
__device__ __align__(16) __nv_bfloat16 g_w2h[OUTC * HIDC]; // W2^T hi  [64 n][256 k]
__device__ __align__(16) __nv_bfloat16 g_w2l[OUTC * HIDC]; // W2^T lo
__device__ float g_dinv[NNODES];
__device__ int   g_deg[NNODES];
__device__ int   g_rowptr[NNODES + 1];
__device__ int   g_pos[NNODES];
__device__ int   g_csr_src[NEDGES];
__device__ float g_csr_nrm[NEDGES];
#define SCAN_NBLK 196
__device__ int   g_part[SCAN_NBLK];

// ================= helpers =================================================
__device__ __forceinline__ uint32_t smem_u32(const void* p) {
    uint32_t a;
    asm("{ .reg .u64 t; cvta.to.shared.u64 t, %1; cvt.u32.u64 %0, t; }" : "=r"(a) : "l"(p));
    return a;
}

__device__ __forceinline__ void ldsm_x4(uint32_t* r, uint32_t addr) {
    asm volatile("ldmatrix.sync.aligned.m8n8.x4.shared.b16 {%0,%1,%2,%3}, [%4];"
        : "=r"(r[0]), "=r"(r[1]), "=r"(r[2]), "=r"(r[3]) : "r"(addr));
}

__device__ __forceinline__ void mma_bf16(float* c, const uint32_t* a,
                                         uint32_t b0, uint32_t b1) {
    asm volatile(
        "mma.sync.aligned.m16n8k16.row.col.f32.bf16.bf16.f32 "
        "{%0,%1,%2,%3}, {%4,%5,%6,%7}, {%8,%9}, {%0,%1,%2,%3};"
        : "+f"(c[0]), "+f"(c[1]), "+f"(c[2]), "+f"(c[3])
        : "r"(a[0]), "r"(a[1]), "r"(a[2]), "r"(a[3]), "r"(b0), "r"(b1));
}

// ---------------- degree / CSR construction -------------------------------
__global__ void k_init_deg() {
    int v = blockIdx.x * blockDim.x + threadIdx.x;
    if (v < NNODES) g_deg[v] = 1;  // self loop
}

__global__ void k_count(const int* __restrict__ dst, int E) {
    int e = blockIdx.x * blockDim.x + threadIdx.x;
    if (e < E) atomicAdd(&g_deg[dst[e]], 1);
}

__global__ void k_dinv() {
    int v = blockIdx.x * blockDim.x + threadIdx.x;
    if (v < NNODES) g_dinv[v] = rsqrtf((float)g_deg[v]);
}

// parallel exclusive scan of (deg-1), 3 kernels
__global__ void k_blocksum() {
    __shared__ int s[256];
    int t = threadIdx.x, v = blockIdx.x * 256 + t;
    s[t] = (v < NNODES) ? g_deg[v] - 1 : 0;
    __syncthreads();
    for (int o = 128; o > 0; o >>= 1) {
        if (t < o) s[t] += s[t + o];
        __syncthreads();
    }
    if (t == 0) g_part[blockIdx.x] = s[0];
}

__global__ void k_scanpart() {
    if (threadIdx.x == 0) {
        int acc = 0;
        for (int i = 0; i < SCAN_NBLK; i++) { int t = g_part[i]; g_part[i] = acc; acc += t; }
    }
}

__global__ void k_rowptr() {
    __shared__ int s[256];
    int b = blockIdx.x, t = threadIdx.x;
    int v = b * 256 + t;
    int e = (v < NNODES) ? g_deg[v] - 1 : 0;
    s[t] = e;
    __syncthreads();
    for (int o = 1; o < 256; o <<= 1) {
        int x = (t >= o) ? s[t - o] : 0;
        __syncthreads();
        s[t] += x;
        __syncthreads();
    }
    int incl = s[t];
    int base = g_part[b];
    if (v < NNODES) { g_rowptr[v] = base + incl - e; g_pos[v] = base + incl - e; }
    if (v == NNODES - 1) g_rowptr[NNODES] = base + incl;
}

__global__ void k_scatter(const int* __restrict__ src,
                          const int* __restrict__ dst, int E) {
    int e = blockIdx.x * blockDim.x + threadIdx.x;
    if (e >= E) return;
    int s = src[e];
    int d = dst[e];
    int p = atomicAdd(&g_pos[d], 1);
    g_csr_src[p] = s;
    g_csr_nrm[p] = g_dinv[s] * g_dinv[d];
}

// ---------------- weight transpose + bf16 hi/lo split ----------------------
__global__ void k_split_w1t(const float* __restrict__ W1) {
    int idx = blockIdx.x * blockDim.x + threadIdx.x;  // over 256*512
    if (idx >= HIDC * INC) return;
    int n = idx >> 9;          // 0..255
    int k = idx & 511;         // 0..511
    float v = W1[k * HIDC + n];
    __nv_bfloat16 h = __float2bfloat16_rn(v);
    float r = v - __bfloat162float(h);
    g_w1h[idx] = h;
    g_w1l[idx] = __float2bfloat16_rn(r);
}

__global__ void k_split_w2t(const float* __restrict__ W2) {
    int idx = blockIdx.x * blockDim.x + threadIdx.x;  // over 64*256
    if (idx >= OUTC * HIDC) return;
    int n = idx >> 8;          // 0..63
    int k = idx & 255;         // 0..255
    float v = W2[k * OUTC + n];
    __nv_bfloat16 h = __float2bfloat16_rn(v);
    float r = v - __bfloat162float(h);
    g_w2h[idx] = h;
    g_w2l[idx] = __float2bfloat16_rn(r);
}

// ---------------- warp-MMA compensated-bf16 GEMM ---------------------------
// C[M,N] = A[M,K] @ B[K,N], A fp32 (converted in-kernel), B pre-split bf16
// hi/lo stored transposed as [N][K]. CTA tile 128x64, 8 warps (4x2), each warp
// 32x32 via m16n8k16. Split: Ah*Bh + Ah*Bl + Al*Bh (fp32 accum) -> ~1e-5 err.
// Smem rows padded to 40 bf16 (80B): ldmatrix 16B phases conflict-free.
#define ASTR 40

template<int K, int N>
__device__ __forceinline__ void gemm_tc_body(const float* __restrict__ A,
                                             const __nv_bfloat16* __restrict__ Bh,
                                             const __nv_bfloat16* __restrict__ Bl,
                                             float* __restrict__ C) {
    __shared__ __align__(16) __nv_bfloat16 sAh[128 * ASTR];
    __shared__ __align__(16) __nv_bfloat16 sAl[128 * ASTR];
    __shared__ __align__(16) __nv_bfloat16 sBh[64 * ASTR];
    __shared__ __align__(16) __nv_bfloat16 sBl[64 * ASTR];

    const int tid = threadIdx.x;
    const int wid = tid >> 5;
    const int lane = tid & 31;
    const int warpM = wid >> 1;   // 0..3 -> 32-row slab
    const int warpN = wid & 1;    // 0..1 -> 32-col slab
    const int rowBase = blockIdx.y * 128;
    const int colBase = blockIdx.x * 64;

    const uint32_t aHiB = smem_u32(sAh);
    const uint32_t aLoB = smem_u32(sAl);
    const uint32_t bHiB = smem_u32(sBh);
    const uint32_t bLoB = smem_u32(sBl);

    float acc[2][4][4];
#pragma unroll
    for (int mi = 0; mi < 2; mi++)
#pragma unroll
        for (int nj = 0; nj < 4; nj++)
#pragma unroll
            for (int q = 0; q < 4; q++) acc[mi][nj][q] = 0.f;

    // ldmatrix lane->address components
    const int aRow = lane & 15;                         // row within 16
    const int aColH = (lane >> 4) * 8;                  // k half: 0 / 8
    const int bRow = ((lane >> 4) << 3) + (lane & 7);   // n within 16
    const int bColH = ((lane >> 3) & 1) * 8;            // k half: 0 / 8

    for (int k0 = 0; k0 < K; k0 += 32) {
        // ---- A tile [128 x 32] fp32 -> bf16 hi/lo, smem stride 40
#pragma unroll
        for (int j = 0; j < 4; j++) {
            int i = tid + j * 256;     // float4 index 0..1023
            int r = i >> 3;            // row 0..127
            int c4 = i & 7;            // float4 within 32 floats
            int gm = rowBase + r;
            float4 v = make_float4(0.f, 0.f, 0.f, 0.f);
            if (gm < NNODES)
                v = *reinterpret_cast<const float4*>(A + (size_t)gm * K + k0 + c4 * 4);
            __nv_bfloat16 h0 = __float2bfloat16_rn(v.x), h1 = __float2bfloat16_rn(v.y);
            __nv_bfloat16 h2 = __float2bfloat16_rn(v.z), h3 = __float2bfloat16_rn(v.w);
            __nv_bfloat16 l0 = __float2bfloat16_rn(v.x - __bfloat162float(h0));
            __nv_bfloat16 l1 = __float2bfloat16_rn(v.y - __bfloat162float(h1));
            __nv_bfloat16 l2 = __float2bfloat16_rn(v.z - __bfloat162float(h2));
            __nv_bfloat16 l3 = __float2bfloat16_rn(v.w - __bfloat162float(h3));
            uint2 hp, lp;
            hp.x = (uint32_t)__bfloat16_as_ushort(h0) | ((uint32_t)__bfloat16_as_ushort(h1) << 16);
            hp.y = (uint32_t)__bfloat16_as_ushort(h2) | ((uint32_t)__bfloat16_as_ushort(h3) << 16);
            lp.x = (uint32_t)__bfloat16_as_ushort(l0) | ((uint32_t)__bfloat16_as_ushort(l1) << 16);
            lp.y = (uint32_t)__bfloat16_as_ushort(l2) | ((uint32_t)__bfloat16_as_ushort(l3) << 16);
            uint32_t off = r * (ASTR * 2) + c4 * 8;   // bytes
            *reinterpret_cast<uint2*>(reinterpret_cast<char*>(sAh) + off) = hp;
            *reinterpret_cast<uint2*>(reinterpret_cast<char*>(sAl) + off) = lp;
        }
        // ---- B tile [64 n x 32 k] bf16 hi/lo (pre-split, [N][K])
        {
            int n = tid >> 2;          // 0..63
            int u = tid & 3;           // 16B unit within 64B row chunk
            const int4* ph = reinterpret_cast<const int4*>(Bh + (size_t)(colBase + n) * K + k0);
            const int4* pl = reinterpret_cast<const int4*>(Bl + (size_t)(colBase + n) * K + k0);
            int4 vh = ph[u];
            int4 vl = pl[u];
            uint32_t off = n * (ASTR * 2) + u * 16;
            *reinterpret_cast<int4*>(reinterpret_cast<char*>(sBh) + off) = vh;
            *reinterpret_cast<int4*>(reinterpret_cast<char*>(sBl) + off) = vl;
        }
        __syncthreads();

#pragma unroll
        for (int kb = 0; kb < 32; kb += 16) {
            uint32_t ah[2][4], al[2][4];
#pragma unroll
            for (int mi = 0; mi < 2; mi++) {
                uint32_t aoff = (uint32_t)(warpM * 32 + mi * 16 + aRow) * (ASTR * 2)
                              + (uint32_t)(kb + aColH) * 2;
                ldsm_x4(ah[mi], aHiB + aoff);
                ldsm_x4(al[mi], aLoB + aoff);
            }
            uint32_t bh[2][4], bl[2][4];
#pragma unroll
            for (int np = 0; np < 2; np++) {
                uint32_t boff = (uint32_t)(warpN * 32 + np * 16 + bRow) * (ASTR * 2)
                              + (uint32_t)(kb + bColH) * 2;
                ldsm_x4(bh[np], bHiB + boff);
                ldsm_x4(bl[np], bLoB + boff);
            }
#pragma unroll
            for (int mi = 0; mi < 2; mi++)
#pragma unroll
                for (int nj = 0; nj < 4; nj++) {
                    int np = nj >> 1, s = (nj & 1) * 2;
                    mma_bf16(acc[mi][nj], ah[mi], bh[np][s], bh[np][s + 1]);
                    mma_bf16(acc[mi][nj], ah[mi], bl[np][s], bl[np][s + 1]);
                    mma_bf16(acc[mi][nj], al[mi], bh[np][s], bh[np][s + 1]);
                }
        }
        __syncthreads();
    }

    // epilogue: c0,c1 -> (row l>>2, cols (l&3)*2,+1); c2,c3 -> row+8
#pragma unroll
    for (int mi = 0; mi < 2; mi++)
#pragma unroll
        for (int nj = 0; nj < 4; nj++) {
            int r0 = rowBase + warpM * 32 + mi * 16 + (lane >> 2);
            int cc = colBase + warpN * 32 + nj * 8 + (lane & 3) * 2;
            if (r0 < NNODES)
                *reinterpret_cast<float2*>(C + (size_t)r0 * N + cc) =
                    make_float2(acc[mi][nj][0], acc[mi][nj][1]);
            int r1 = r0 + 8;
            if (r1 < NNODES)
                *reinterpret_cast<float2*>(C + (size_t)r1 * N + cc) =
                    make_float2(acc[mi][nj][2], acc[mi][nj][3]);
        }
}

__global__ __launch_bounds__(256) void k_gemm1_mma(const float* __restrict__ x) {
    gemm_tc_body<INC, HIDC>(x, g_w1h, g_w1l, g_h1);
}

__global__ __launch_bounds__(256) void k_gemm2_mma() {
    gemm_tc_body<HIDC, OUTC>(g_a1, g_w2h, g_w2l, g_h2);
}

// ---------------- layer-1 aggregation: warp per node, 256 channels --------
__global__ __launch_bounds__(256) void k_agg1(const float* __restrict__ b1) {
    int warp = (blockIdx.x * blockDim.x + threadIdx.x) >> 5;
    int lane = threadIdx.x & 31;
    if (warp >= NNODES) return;
    const int v = warp;

    float4 acc0 = make_float4(0.f, 0.f, 0.f, 0.f);
    float4 acc1 = acc0;

    const int beg = g_rowptr[v];
    const int end = g_rowptr[v + 1];
    for (int e = beg; e < end; e++) {
        int s = g_csr_src[e];
        float w = g_csr_nrm[e];
        const float4* hs = reinterpret_cast<const float4*>(g_h1 + (size_t)s * HIDC);
        float4 x0 = hs[lane];
        float4 x1 = hs[32 + lane];
        acc0.x += w * x0.x; acc0.y += w * x0.y; acc0.z += w * x0.z; acc0.w += w * x0.w;
        acc1.x += w * x1.x; acc1.y += w * x1.y; acc1.z += w * x1.z; acc1.w += w * x1.w;
    }
    {
        float dv = g_dinv[v];
        float w = dv * dv;
        const float4* hv = reinterpret_cast<const float4*>(g_h1 + (size_t)v * HIDC);
        float4 x0 = hv[lane];
        float4 x1 = hv[32 + lane];
        acc0.x += w * x0.x; acc0.y += w * x0.y; acc0.z += w * x0.z; acc0.w += w * x0.w;
        acc1.x += w * x1.x; acc1.y += w * x1.y; acc1.z += w * x1.z; acc1.w += w * x1.w;
    }
    const float4* bb = reinterpret_cast<const float4*>(b1);
    float4 c0 = bb[lane];
    float4 c1 = bb[32 + lane];
    float4 o0 = make_float4(fmaxf(acc0.x + c0.x, 0.f), fmaxf(acc0.y + c0.y, 0.f),
                            fmaxf(acc0.z + c0.z, 0.f), fmaxf(acc0.w + c0.w, 0.f));
    float4 o1 = make_float4(fmaxf(acc1.x + c1.x, 0.f), fmaxf(acc1.y + c1.y, 0.f),
                            fmaxf(acc1.z + c1.z, 0.f), fmaxf(acc1.w + c1.w, 0.f));
    float4* outp = reinterpret_cast<float4*>(g_a1 + (size_t)v * HIDC);
    outp[lane] = o0;
    outp[32 + lane] = o1;
}

// ------- layer-2 aggregation + bias + log_softmax, warp per node ----------
__global__ __launch_bounds__(256) void k_agg2(const float* __restrict__ b2,
                                              float* __restrict__ out) {
    int warp = (blockIdx.x * blockDim.x + threadIdx.x) >> 5;
    int lane = threadIdx.x & 31;
    if (warp >= NNODES) return;
    const int v = warp;

    float2 acc = make_float2(0.f, 0.f);
    const int beg = g_rowptr[v];
    const int end = g_rowptr[v + 1];
    for (int e = beg; e < end; e++) {
        int s = g_csr_src[e];
        float w = g_csr_nrm[e];
        const float2* hs = reinterpret_cast<const float2*>(g_h2 + (size_t)s * OUTC);
        float2 x = hs[lane];
        acc.x += w * x.x;
        acc.y += w * x.y;
    }
    {
        float dv = g_dinv[v];
        float w = dv * dv;
        const float2* hv = reinterpret_cast<const float2*>(g_h2 + (size_t)v * OUTC);
        float2 x = hv[lane];
        acc.x += w * x.x;
        acc.y += w * x.y;
    }
    const float2* bb = reinterpret_cast<const float2*>(b2);
    float2 c = bb[lane];
    float v0 = acc.x + c.x;
    float v1 = acc.y + c.y;

    float m = fmaxf(v0, v1);
#pragma unroll
    for (int o = 16; o > 0; o >>= 1) m = fmaxf(m, __shfl_xor_sync(0xFFFFFFFFu, m, o));
    float s = expf(v0 - m) + expf(v1 - m);
#pragma unroll
    for (int o = 16; o > 0; o >>= 1) s += __shfl_xor_sync(0xFFFFFFFFu, s, o);
    float ls = logf(s);

    float2 ov = make_float2(v0 - m - ls, v1 - m - ls);
    reinterpret_cast<float2*>(out)[(size_t)v * 32 + lane] = ov;
}

// ---------------- launch --------------------------------------------------
extern "C" void kernel_launch(void* const* d_in, const int* in_sizes, int n_in,
                              void* d_out, int out_size) {
    const float* x  = (const float*)d_in[0];
    const int*   ei = (const int*)d_in[1];
    const float* W1 = (const float*)d_in[2];
    const float* b1 = (const float*)d_in[3];
    const float* W2 = (const float*)d_in[4];
    const float* b2 = (const float*)d_in[5];
    float* out = (float*)d_out;

    const int E = in_sizes[1] / 2;  // 800000
    const int* src = ei;
    const int* dst = ei + E;

    const int TB = 256;
    const int nodeBlocks = (NNODES + TB - 1) / TB;
    const int edgeBlocks = (E + TB - 1) / TB;
    const int warpBlocks = (NNODES * 32 + TB - 1) / TB;

    // CSR build
    k_init_deg<<<nodeBlocks, TB>>>();
    k_count<<<edgeBlocks, TB>>>(dst, E);
    k_dinv<<<nodeBlocks, TB>>>();
    k_blocksum<<<SCAN_NBLK, 256>>>();
    k_scanpart<<<1, 32>>>();
    k_rowptr<<<SCAN_NBLK, 256>>>();
    k_scatter<<<edgeBlocks, TB>>>(src, dst, E);

    // weight prep (transpose + bf16 hi/lo split)
    k_split_w1t<<<(HIDC * INC + TB - 1) / TB, TB>>>(W1);
    k_split_w2t<<<(OUTC * HIDC + TB - 1) / TB, TB>>>(W2);

    // layer 1: warp-MMA GEMM + aggregation
    dim3 g1(HIDC / 64, (NNODES + 127) / 128);
    k_gemm1_mma<<<g1, 256>>>(x);
    k_agg1<<<warpBlocks, TB>>>(b1);

    // layer 2: warp-MMA GEMM + aggregation/softmax
    dim3 g2(OUTC / 64, (NNODES + 127) / 128);
    k_gemm2_mma<<<g2, 256>>>();
    k_agg2<<<warpBlocks, TB>>>(b2, out);
}